// round 6
// baseline (speedup 1.0000x reference)
#include <cuda_runtime.h>
#include <cuda_bf16.h>
#include <math.h>
#include <stdint.h>

// Problem constants
#define B_SZ    512
#define DFEAT   2048
#define DATTR   312
#define DATTR_P 320              // N padded to 5*64

// GEMM tiling: D[512,320] = X[512,2048] @ W^T, bf16 hi/lo x4-term split
#define MT_BLK  128              // M per CTA
#define NT_BLK  64               // N per CTA
#define BKT     32               // K per smem tile
#define KSPLIT  8
#define KSLICE  (DFEAT / KSPLIT) // 256

// Scratch (__device__ globals: allocation-free, zero-initialized at load)
__device__ __nv_bfloat16 g_WhiT[DATTR_P * DFEAT];   // W^T K-major; rows >=312 stay 0
__device__ __nv_bfloat16 g_WloT[DATTR_P * DFEAT];
__device__ float g_partial[KSPLIT][B_SZ][DATTR_P];
__device__ float g_Sf[B_SZ];
__device__ unsigned int g_done;                     // last-block counter (reset each call)

// ---------------------------------------------------------------------------
// Kernel 0: transpose W [2048,312] -> W^T [320,2048] with bf16 hi/lo split
// ---------------------------------------------------------------------------
__global__ void split_w_kernel(const float* __restrict__ Wm)
{
    __shared__ float t[32][33];
    const int n0 = blockIdx.x * 32, k0 = blockIdx.y * 32;
    const int tx = threadIdx.x, ty = threadIdx.y;   // 32 x 8

    #pragma unroll
    for (int r = 0; r < 32; r += 8) {
        const int n = n0 + tx, k = k0 + ty + r;
        t[ty + r][tx] = (n < DATTR) ? Wm[(size_t)k * DATTR + n] : 0.f;
    }
    __syncthreads();
    #pragma unroll
    for (int r = 0; r < 32; r += 8) {
        const int n = n0 + ty + r, k = k0 + tx;
        if (n < DATTR) {
            const float v = t[tx][ty + r];
            const __nv_bfloat16 h = __float2bfloat16_rn(v);
            const __nv_bfloat16 l = __float2bfloat16_rn(v - __bfloat162float(h));
            g_WhiT[(size_t)n * DFEAT + k] = h;
            g_WloT[(size_t)n * DFEAT + k] = l;
        }
    }
}

// ---------------------------------------------------------------------------
// Kernel 1: fused bf16 mma.sync GEMM with inline X hi/lo split.
// grid (5 n-tiles, 4 m-tiles, 8 k-slices) = 160 CTAs, 256 threads (8 warps).
// Warp grid 4(m) x 2(n); warp tile 32x32 = 2x4 atoms; 4 mma chains (hi/lo^2).
// ---------------------------------------------------------------------------
__global__ __launch_bounds__(256) void mma_gemm_kernel(const float* __restrict__ X)
{
    __shared__ __nv_bfloat16 sAhi[MT_BLK][40];   // stride 40: conflict-light
    __shared__ __nv_bfloat16 sAlo[MT_BLK][40];
    __shared__ __nv_bfloat16 sBhi[NT_BLK][40];
    __shared__ __nv_bfloat16 sBlo[NT_BLK][40];

    const int tid   = threadIdx.x;
    const int wid   = tid >> 5;
    const int lane  = tid & 31;
    const int warpM = wid >> 1;          // 0..3
    const int warpN = wid & 1;           // 0..1
    const int nt = blockIdx.x, mt = blockIdx.y, zs = blockIdx.z;

    const int mBase = mt * MT_BLK;
    const int nBase = nt * NT_BLK;
    const int k0    = zs * KSLICE;

    const int lq = lane >> 2;   // 0..7
    const int lr = lane & 3;    // 0..3

    // prefetch registers
    float4 xa[4];
    uint4  wh, wl;
    const int arow = tid >> 3, ac = tid & 7;    // A: 8 float4 per 32-k row
    const int wrow = tid >> 2, wc = tid & 3;    // B: 4 uint4 per 32-k row

    float acc[2][4][4] = {};

    // tile 0 prefetch
    {
        const int k = k0;
        #pragma unroll
        for (int it = 0; it < 4; it++)
            xa[it] = *(const float4*)(X + (size_t)(mBase + arow + 32 * it) * DFEAT + k + ac * 4);
        wh = *(const uint4*)(g_WhiT + (size_t)(nBase + wrow) * DFEAT + k + wc * 8);
        wl = *(const uint4*)(g_WloT + (size_t)(nBase + wrow) * DFEAT + k + wc * 8);
    }

    for (int kt = 0; kt < KSLICE; kt += BKT) {
        // store prefetched tile to smem (convert X to hi/lo)
        #pragma unroll
        for (int it = 0; it < 4; it++) {
            const float4 v = xa[it];
            const int row = arow + 32 * it;
            const __nv_bfloat16 h0 = __float2bfloat16_rn(v.x), h1 = __float2bfloat16_rn(v.y);
            const __nv_bfloat16 h2 = __float2bfloat16_rn(v.z), h3 = __float2bfloat16_rn(v.w);
            *(__nv_bfloat162*)&sAhi[row][ac * 4]     = __nv_bfloat162(h0, h1);
            *(__nv_bfloat162*)&sAhi[row][ac * 4 + 2] = __nv_bfloat162(h2, h3);
            *(__nv_bfloat162*)&sAlo[row][ac * 4] = __nv_bfloat162(
                __float2bfloat16_rn(v.x - __bfloat162float(h0)),
                __float2bfloat16_rn(v.y - __bfloat162float(h1)));
            *(__nv_bfloat162*)&sAlo[row][ac * 4 + 2] = __nv_bfloat162(
                __float2bfloat16_rn(v.z - __bfloat162float(h2)),
                __float2bfloat16_rn(v.w - __bfloat162float(h3)));
        }
        *(uint4*)&sBhi[wrow][wc * 8] = wh;
        *(uint4*)&sBlo[wrow][wc * 8] = wl;
        __syncthreads();

        // prefetch next tile while mma runs
        if (kt + BKT < KSLICE) {
            const int k = k0 + kt + BKT;
            #pragma unroll
            for (int it = 0; it < 4; it++)
                xa[it] = *(const float4*)(X + (size_t)(mBase + arow + 32 * it) * DFEAT + k + ac * 4);
            wh = *(const uint4*)(g_WhiT + (size_t)(nBase + wrow) * DFEAT + k + wc * 8);
            wl = *(const uint4*)(g_WloT + (size_t)(nBase + wrow) * DFEAT + k + wc * 8);
        }

        #pragma unroll
        for (int kk = 0; kk < BKT; kk += 16) {
            uint32_t ahi[2][4], alo[2][4];
            #pragma unroll
            for (int am = 0; am < 2; am++) {
                const int r = warpM * 32 + am * 16 + lq;
                ahi[am][0] = *(const uint32_t*)&sAhi[r    ][kk + lr * 2    ];
                ahi[am][1] = *(const uint32_t*)&sAhi[r + 8][kk + lr * 2    ];
                ahi[am][2] = *(const uint32_t*)&sAhi[r    ][kk + lr * 2 + 8];
                ahi[am][3] = *(const uint32_t*)&sAhi[r + 8][kk + lr * 2 + 8];
                alo[am][0] = *(const uint32_t*)&sAlo[r    ][kk + lr * 2    ];
                alo[am][1] = *(const uint32_t*)&sAlo[r + 8][kk + lr * 2    ];
                alo[am][2] = *(const uint32_t*)&sAlo[r    ][kk + lr * 2 + 8];
                alo[am][3] = *(const uint32_t*)&sAlo[r + 8][kk + lr * 2 + 8];
            }
            uint32_t bhi[4][2], blo[4][2];
            #pragma unroll
            for (int bn = 0; bn < 4; bn++) {
                const int n = warpN * 32 + bn * 8 + lq;
                bhi[bn][0] = *(const uint32_t*)&sBhi[n][kk + lr * 2    ];
                bhi[bn][1] = *(const uint32_t*)&sBhi[n][kk + lr * 2 + 8];
                blo[bn][0] = *(const uint32_t*)&sBlo[n][kk + lr * 2    ];
                blo[bn][1] = *(const uint32_t*)&sBlo[n][kk + lr * 2 + 8];
            }
            #pragma unroll
            for (int am = 0; am < 2; am++) {
                #pragma unroll
                for (int bn = 0; bn < 4; bn++) {
                    float* c = acc[am][bn];
                    #define MMA(AV, BV)                                               \
                        asm volatile(                                                  \
                            "mma.sync.aligned.m16n8k16.row.col.f32.bf16.bf16.f32 "    \
                            "{%0,%1,%2,%3}, {%4,%5,%6,%7}, {%8,%9}, {%0,%1,%2,%3};"   \
                            : "+f"(c[0]), "+f"(c[1]), "+f"(c[2]), "+f"(c[3])           \
                            : "r"(AV[0]), "r"(AV[1]), "r"(AV[2]), "r"(AV[3]),          \
                              "r"(BV[0]), "r"(BV[1]))
                    MMA(ahi[am], bhi[bn]);
                    MMA(ahi[am], blo[bn]);
                    MMA(alo[am], bhi[bn]);
                    MMA(alo[am], blo[bn]);
                    #undef MMA
                }
            }
        }
        __syncthreads();
    }

    // Epilogue: write fp32 partials
    #pragma unroll
    for (int am = 0; am < 2; am++) {
        const int row0 = mBase + warpM * 32 + am * 16 + lq;
        #pragma unroll
        for (int bn = 0; bn < 4; bn++) {
            const int col = nBase + warpN * 32 + bn * 8 + lr * 2;
            *(float2*)&g_partial[zs][row0    ][col] = make_float2(acc[am][bn][0], acc[am][bn][1]);
            *(float2*)&g_partial[zs][row0 + 8][col] = make_float2(acc[am][bn][2], acc[am][bn][3]);
        }
    }
}

// ---------------------------------------------------------------------------
// Kernel 2 (fused): per-row S[i], then last block computes the pair loss.
// grid 512, block 128.
// ---------------------------------------------------------------------------
__global__ __launch_bounds__(128) void rowstats_pair_kernel(
    const float* __restrict__ bvec, const int* __restrict__ labw,
    float* __restrict__ out)
{
    const int i   = blockIdx.x;
    const int tid = threadIdx.x;

    __shared__ float vals[DATTR_P];
    __shared__ float sred[4];

    // float4 partial reduction: 80 float4 cols, 8 slices each (MLP=8)
    if (tid < 80) {
        float4 a = (tid < 78) ? *(const float4*)(bvec + tid * 4)
                              : make_float4(0.f, 0.f, 0.f, 0.f);
        #pragma unroll
        for (int s = 0; s < KSPLIT; s++) {
            const float4 p = *(const float4*)&g_partial[s][i][tid * 4];
            a.x += p.x; a.y += p.y; a.z += p.z; a.w += p.w;
        }
        *(float4*)&vals[tid * 4] = a;
    }
    __syncthreads();

    // row max over first 312 cols
    float m = -1e30f;
    for (int c = tid; c < DATTR; c += 128) m = fmaxf(m, vals[c]);
    #pragma unroll
    for (int o = 16; o; o >>= 1) m = fmaxf(m, __shfl_xor_sync(0xffffffffu, m, o));
    if ((tid & 31) == 0) sred[tid >> 5] = m;
    __syncthreads();
    m = fmaxf(fmaxf(sred[0], sred[1]), fmaxf(sred[2], sred[3]));

    __shared__ float sse[4], srs[4];
    float se = 0.f, rs = 0.f;
    for (int c = tid; c < DATTR; c += 128) {
        const float v = vals[c];
        se += expf(v - m);
        rs += v;
    }
    #pragma unroll
    for (int o = 16; o; o >>= 1) {
        se += __shfl_xor_sync(0xffffffffu, se, o);
        rs += __shfl_xor_sync(0xffffffffu, rs, o);
    }
    if ((tid & 31) == 0) { sse[tid >> 5] = se; srs[tid >> 5] = rs; }
    __syncthreads();

    if (tid == 0) {
        const float seT = sse[0] + sse[1] + sse[2] + sse[3];
        const float rsT = srs[0] + srs[1] + srs[2] + srs[3];
        g_Sf[i] = rsT - (float)DATTR * (m + logf(seT));
    }

    // ---- last-block pair loss ----
    __shared__ int s_last;
    __threadfence();
    if (tid == 0) {
        const unsigned int old = atomicAdd(&g_done, 1u);
        s_last = (old == (unsigned int)(gridDim.x - 1));
    }
    __syncthreads();
    if (!s_last) return;

    __shared__ int   slab[B_SZ];
    __shared__ float sS[B_SZ];
    __shared__ int   s_not64;
    __shared__ float swsum[4];
    __shared__ unsigned int swcnt[4];

    if (tid == 0) s_not64 = 0;
    __syncthreads();
    // label dtype sniff: int64 buffers have zero odd words (labels < 150)
    for (int t = tid; t < 256; t += 128)
        if (labw[2 * t + 1] != 0) atomicOr(&s_not64, 1);
    __syncthreads();
    const bool is64 = (s_not64 == 0);
    for (int t = tid; t < B_SZ; t += 128) {
        slab[t] = is64 ? labw[2 * t] : labw[t];
        sS[t]   = __ldcg(&g_Sf[t]);
    }
    __syncthreads();

    float        local = 0.f;
    unsigned int cnt   = 0;
    for (int ii = tid; ii < B_SZ; ii += 128) {
        const int   li = slab[ii];
        const float Si = sS[ii];
        for (int j = ii + 1; j < B_SZ; j++)
            if (slab[j] == li) { local += sS[j] - Si; cnt++; }
    }
    #pragma unroll
    for (int o = 16; o; o >>= 1) {
        local += __shfl_xor_sync(0xffffffffu, local, o);
        cnt   += __shfl_xor_sync(0xffffffffu, cnt, o);
    }
    if ((tid & 31) == 0) { swsum[tid >> 5] = local; swcnt[tid >> 5] = cnt; }
    __syncthreads();

    if (tid == 0) {
        const float        s = swsum[0] + swsum[1] + swsum[2] + swsum[3];
        const unsigned int c = swcnt[0] + swcnt[1] + swcnt[2] + swcnt[3];
        out[0] = (c > 0) ? (s / (float)c) : s;
        g_done = 0;   // reset for next graph replay (deterministic)
    }
}

// ---------------------------------------------------------------------------
extern "C" void kernel_launch(void* const* d_in, const int* in_sizes, int n_in,
                              void* d_out, int out_size)
{
    const float* x   = (const float*)d_in[0];      // [512, 2048]
    const float* Wm  = (const float*)d_in[1];      // [2048, 312]
    const float* b   = (const float*)d_in[2];      // [312]
    // d_in[3] = seen_att : unused (cancels exactly for same-label pairs)
    const int*   lab = (const int*)d_in[4];        // [512] labels

    split_w_kernel<<<dim3(10, 64), dim3(32, 8)>>>(Wm);
    mma_gemm_kernel<<<dim3(5, 4, KSPLIT), 256>>>(x);
    rowstats_pair_kernel<<<B_SZ, 128>>>(b, lab, (float*)d_out);
}